// round 7
// baseline (speedup 1.0000x reference)
#include <cuda_runtime.h>
#include <math.h>
#include <stdint.h>

// Problem constants
#define NB    2
#define L     2048
#define DIM   512
#define H     8
#define D     64
#define NH    (NB*H)          // 16
#define ROWS  (NB*L)          // 4096
#define C     64              // chunk length
#define NC    (L/C)           // 32 chunks
#define STSZ  (D*D + D)       // 4160 floats per chunk state

// Scratch (device globals; allocation-free)
__device__ float g_q[NH * L * D];
__device__ float g_k[NH * L * D];
__device__ float g_v[NH * L * D];
__device__ float g_state[NH * NC * STSZ];
__device__ float g_prefix[NH * NC * STSZ];
__device__ float g_xr[2 * ROWS * DIM];     // tf32-rounded query | key_seq
__device__ float g_wr[3 * DIM * DIM];      // tf32-rounded Wq | Wk | Wv

__device__ __forceinline__ float softplus_f(float x) {
    return (x > 20.0f) ? x : log1pf(__expf(x));
}

__device__ __forceinline__ float tf32_round(float x) {
    unsigned u;
    asm("cvt.rna.tf32.f32 %0, %1;" : "=r"(u) : "f"(x));
    return __uint_as_float(u);
}

__device__ __forceinline__ void cp16(uint32_t dst, const float* src) {
    asm volatile("cp.async.cg.shared.global [%0], [%1], 16;" :: "r"(dst), "l"(src));
}
__device__ __forceinline__ void cp_commit() {
    asm volatile("cp.async.commit_group;");
}

#define MMA_TF32(ACC, A0, A1, A2, A3, B0, B1)                                  \
    asm volatile(                                                              \
        "mma.sync.aligned.m16n8k8.row.col.f32.tf32.tf32.f32 "                 \
        "{%0,%1,%2,%3}, {%4,%5,%6,%7}, {%8,%9}, {%0,%1,%2,%3};"               \
        : "+f"((ACC)[0]), "+f"((ACC)[1]), "+f"((ACC)[2]), "+f"((ACC)[3])       \
        : "r"(A0), "r"(A1), "r"(A2), "r"(A3), "r"(B0), "r"(B1))

// ---------------------------------------------------------------------------
// Dummy kernel: shifts launch positions so ncu (which captures launch #4)
// profiles gemm_proj_tc next round.
// ---------------------------------------------------------------------------
__global__ void dummy_kernel() {}

// ---------------------------------------------------------------------------
// Kernel 0: pre-round inputs to nearest-tf32.
// ---------------------------------------------------------------------------
__global__ void prep_kernel(const float* __restrict__ query,
                            const float* __restrict__ key_seq,
                            const float* __restrict__ Wq,
                            const float* __restrict__ Wk,
                            const float* __restrict__ Wv) {
    const int XQ4 = ROWS * DIM / 4;
    const int W4  = DIM * DIM / 4;
    int idx = blockIdx.x * blockDim.x + threadIdx.x;

    const float* src;
    float* dst;
    if (idx < 2 * XQ4) {
        src = (idx < XQ4) ? query + idx * 4 : key_seq + (idx - XQ4) * 4;
        dst = g_xr + idx * 4;
    } else {
        int w = idx - 2 * XQ4;
        int wi = w / W4;
        const float* ws[3] = {Wq, Wk, Wv};
        src = ws[wi] + (w - wi * W4) * 4;
        dst = g_wr + w * 4;
    }
    float4 v = *(const float4*)src;
    v.x = tf32_round(v.x); v.y = tf32_round(v.y);
    v.z = tf32_round(v.z); v.w = tf32_round(v.w);
    *(float4*)dst = v;
}

// ---------------------------------------------------------------------------
// Kernel 1: merged TF32 GEMM, 3-stage cp.async pipeline.
// Block tile 128x128, K-tile 32, 256 threads, warp tile 64x32.
// ---------------------------------------------------------------------------
#define XPAD 36
#define TILEF (128 * XPAD)
#define STAGEF (2 * TILEF)
#define NSTAGE 3
#define GEMM_SMEM (NSTAGE * STAGEF * 4)   // 110592 B

__global__ void __launch_bounds__(256, 2)
gemm_proj_tc(float* __restrict__ out_q,
             float* __restrict__ out_k,
             float* __restrict__ out_v) {
    extern __shared__ float sm[];

    const int tid  = threadIdx.x;
    const int lane = tid & 31;
    const int warp = tid >> 5;
    const int wm = warp >> 2;
    const int wn = warp & 3;
    const int g  = lane >> 2;
    const int tg = lane & 3;

    const int z = blockIdx.z;
    const int rowBase = blockIdx.y * 128;
    const int colBase = blockIdx.x * 128;

    const float* Xg = g_xr + (z == 0 ? 0 : ROWS * DIM) + rowBase * DIM;
    const float* Wg = g_wr + z * DIM * DIM + colBase * DIM;
    float* out = (z == 0) ? out_q : (z == 1) ? out_k : out_v;
    const bool do_sp = (z < 2);

    uint32_t smem_u32;
    asm("{ .reg .u64 t; cvta.to.shared.u64 t, %1; cvt.u32.u64 %0, t; }"
        : "=r"(smem_u32) : "l"(sm));

    const int cr = tid >> 1;
    const int ch = (tid & 1) * 16;
    const float* xs_base = Xg + cr * DIM + ch;
    const float* ws_base = Wg + cr * DIM + ch;
    const uint32_t xd_base = smem_u32 + (cr * XPAD + ch) * 4;
    const uint32_t wd_base = smem_u32 + (TILEF + cr * XPAD + ch) * 4;

    const int NT = DIM / 32;   // 16 K-tiles

    // prologue: issue stages 0 and 1
    #pragma unroll
    for (int p = 0; p < 2; p++) {
        uint32_t so = p * STAGEF * 4;
        #pragma unroll
        for (int s = 0; s < 4; s++) {
            cp16(xd_base + so + s * 16, xs_base + p * 32 + s * 4);
            cp16(wd_base + so + s * 16, ws_base + p * 32 + s * 4);
        }
        cp_commit();
    }

    float acc[4][4][4];
    #pragma unroll
    for (int a = 0; a < 4; a++)
        #pragma unroll
        for (int b = 0; b < 4; b++)
            #pragma unroll
            for (int r = 0; r < 4; r++) acc[a][b][r] = 0.0f;

    int buf = 0;
    for (int t = 0; t < NT; t++) {
        if (t + 1 < NT) {
            asm volatile("cp.async.wait_group 1;");
        } else {
            asm volatile("cp.async.wait_group 0;");
        }
        __syncthreads();

        const float* Xs = sm + buf * STAGEF;
        const float* Ws = Xs + TILEF;

        // issue stage t+2 (writes buffer (t+2)%3, which all warps finished
        // reading in iteration t-1 — guaranteed by the syncthreads above)
        if (t + 2 < NT) {
            uint32_t so = ((buf + 2) % NSTAGE) * STAGEF * 4;
            const float* xs = xs_base + (t + 2) * 32;
            const float* ws = ws_base + (t + 2) * 32;
            #pragma unroll
            for (int s = 0; s < 4; s++) {
                cp16(xd_base + so + s * 16, xs + s * 4);
                cp16(wd_base + so + s * 16, ws + s * 4);
            }
            cp_commit();
        }

        #pragma unroll
        for (int kf = 0; kf < 4; kf++) {
            const int kc = kf * 8 + tg;
            unsigned afr[4][4], bfr[4][2];
            #pragma unroll
            for (int mf = 0; mf < 4; mf++) {
                const float* a = Xs + (wm * 64 + mf * 16 + g) * XPAD + kc;
                afr[mf][0] = __float_as_uint(a[0]);
                afr[mf][1] = __float_as_uint(a[8 * XPAD]);
                afr[mf][2] = __float_as_uint(a[4]);
                afr[mf][3] = __float_as_uint(a[8 * XPAD + 4]);
            }
            #pragma unroll
            for (int nf = 0; nf < 4; nf++) {
                const float* b = Ws + (wn * 32 + nf * 8 + g) * XPAD + kc;
                bfr[nf][0] = __float_as_uint(b[0]);
                bfr[nf][1] = __float_as_uint(b[4]);
            }
            #pragma unroll
            for (int mf = 0; mf < 4; mf++)
                #pragma unroll
                for (int nf = 0; nf < 4; nf++)
                    MMA_TF32(acc[mf][nf], afr[mf][0], afr[mf][1], afr[mf][2],
                             afr[mf][3], bfr[nf][0], bfr[nf][1]);
        }
        buf = (buf + 1) % NSTAGE;
    }

    #pragma unroll
    for (int mf = 0; mf < 4; mf++) {
        #pragma unroll
        for (int nf = 0; nf < 4; nf++) {
            int col = colBase + wn * 32 + nf * 8 + tg * 2;
            int h = col >> 6;
            int dd = col & 63;
            #pragma unroll
            for (int half = 0; half < 2; half++) {
                int row = rowBase + wm * 64 + mf * 16 + half * 8 + g;
                int n = row >> 11;
                int l = row & (L - 1);
                float v0 = acc[mf][nf][half * 2 + 0];
                float v1 = acc[mf][nf][half * 2 + 1];
                if (do_sp) { v0 = softplus_f(v0); v1 = softplus_f(v1); }
                float2 o; o.x = v0; o.y = v1;
                *(float2*)&out[((n * H + h) * L + l) * D + dd] = o;
            }
        }
    }
}

// ---------------------------------------------------------------------------
// Kernel 2: per-chunk state via tensor cores (unchanged from R6).
// ---------------------------------------------------------------------------
#define AP 68

__global__ void __launch_bounds__(128, 2) chunk_state_tc() {
    __shared__ float pkT[64][AP];   // [dk][t]
    __shared__ float vT[64][AP];    // [dv][t]

    const int tid = threadIdx.x;
    const int lane = tid & 31;
    const int warp = tid >> 5;
    const int g = lane >> 2;
    const int tg = lane & 3;
    const int cc = blockIdx.x;
    const int nh = blockIdx.y;

    const float* kbase = g_k + (nh * L + cc * C) * D;
    const float* vbase = g_v + (nh * L + cc * C) * D;

    const int r = tid >> 1;
    const int c0 = (tid & 1) * 32;
    #pragma unroll
    for (int i = 0; i < 8; i++) {
        int c = c0 + i * 4;
        float4 kv = *(const float4*)&kbase[r * D + c];
        pkT[c + 0][r] = tf32_round(kv.x); pkT[c + 1][r] = tf32_round(kv.y);
        pkT[c + 2][r] = tf32_round(kv.z); pkT[c + 3][r] = tf32_round(kv.w);
        float4 vv = *(const float4*)&vbase[r * D + c];
        vT[c + 0][r] = tf32_round(vv.x); vT[c + 1][r] = tf32_round(vv.y);
        vT[c + 2][r] = tf32_round(vv.z); vT[c + 3][r] = tf32_round(vv.w);
    }
    __syncthreads();

    const int rbase = warp * 16;
    float acc[8][4];
    #pragma unroll
    for (int nf = 0; nf < 8; nf++)
        #pragma unroll
        for (int q = 0; q < 4; q++) acc[nf][q] = 0.0f;

    #pragma unroll
    for (int kf = 0; kf < 8; kf++) {
        const int kc = kf * 8 + tg;
        const float* ap = &pkT[rbase + g][kc];
        unsigned a0 = __float_as_uint(ap[0]);
        unsigned a1 = __float_as_uint(ap[8 * AP]);
        unsigned a2 = __float_as_uint(ap[4]);
        unsigned a3 = __float_as_uint(ap[8 * AP + 4]);
        #pragma unroll
        for (int nf = 0; nf < 8; nf++) {
            const float* bp = &vT[nf * 8 + g][kc];
            unsigned b0 = __float_as_uint(bp[0]);
            unsigned b1 = __float_as_uint(bp[4]);
            MMA_TF32(acc[nf], a0, a1, a2, a3, b0, b1);
        }
    }

    float* sbase = g_state + (nh * NC + cc) * STSZ;
    #pragma unroll
    for (int nf = 0; nf < 8; nf++) {
        int dv = nf * 8 + tg * 2;
        #pragma unroll
        for (int half = 0; half < 2; half++) {
            int dk = rbase + half * 8 + g;
            float2 o; o.x = acc[nf][half * 2]; o.y = acc[nf][half * 2 + 1];
            *(float2*)&sbase[dk * D + dv] = o;
        }
    }

    if (tid < 64) {
        float s = 0.0f;
        #pragma unroll 16
        for (int t = 0; t < C; t++) s += pkT[tid][t];
        sbase[D * D + tid] = s;
    }
}

// ---------------------------------------------------------------------------
// Kernel 3: exclusive prefix scan, loads batched for MLP (unchanged).
// ---------------------------------------------------------------------------
__global__ void scan_states_kernel() {
    const int nh = blockIdx.x;
    const int idx = blockIdx.y * 256 + threadIdx.x;
    if (idx >= STSZ) return;
    const int base = nh * NC * STSZ + idx;
    float vals[NC];
    #pragma unroll
    for (int cc = 0; cc < NC; cc++)
        vals[cc] = g_state[base + cc * STSZ];
    float run = 0.0f;
    #pragma unroll
    for (int cc = 0; cc < NC; cc++) {
        g_prefix[base + cc * STSZ] = run;
        run += vals[cc];
    }
}

// ---------------------------------------------------------------------------
// Kernel 4: per-chunk output via tensor cores (unchanged from R6).
// ---------------------------------------------------------------------------
#define SMEM_ATTN2 ((5 * 64 * AP + 3 * 64) * 4)

__global__ void __launch_bounds__(128, 2) attn_out_tc(float* __restrict__ out) {
    extern __shared__ float sm[];
    float* Qf = sm;
    float* Kf = Qf + 64 * AP;
    float* VT = Kf + 64 * AP;
    float* ST = VT + 64 * AP;
    float* Af = ST + 64 * AP;
    float* rs  = Af + 64 * AP;
    float* ssm = rs + 64;
    float* dinv= ssm + 64;

    const int tid = threadIdx.x;
    const int lane = tid & 31;
    const int warp = tid >> 5;
    const int g = lane >> 2;
    const int tg = lane & 3;
    const int cc = blockIdx.x;
    const int nh = blockIdx.y;

    const float* qbase = g_q + (nh * L + cc * C) * D;
    const float* kbase = g_k + (nh * L + cc * C) * D;
    const float* vbase = g_v + (nh * L + cc * C) * D;
    const float* pbase = g_prefix + (nh * NC + cc) * STSZ;

    const int r = tid >> 1;
    const int c0 = (tid & 1) * 32;
    #pragma unroll
    for (int i = 0; i < 8; i++) {
        int c = c0 + i * 4;
        float4 qv = *(const float4*)&qbase[r * D + c];
        qv.x = tf32_round(qv.x); qv.y = tf32_round(qv.y);
        qv.z = tf32_round(qv.z); qv.w = tf32_round(qv.w);
        *(float4*)&Qf[r * AP + c] = qv;
        float4 kv = *(const float4*)&kbase[r * D + c];
        kv.x = tf32_round(kv.x); kv.y = tf32_round(kv.y);
        kv.z = tf32_round(kv.z); kv.w = tf32_round(kv.w);
        *(float4*)&Kf[r * AP + c] = kv;
        float4 vv = *(const float4*)&vbase[r * D + c];
        VT[(c + 0) * AP + r] = tf32_round(vv.x);
        VT[(c + 1) * AP + r] = tf32_round(vv.y);
        VT[(c + 2) * AP + r] = tf32_round(vv.z);
        VT[(c + 3) * AP + r] = tf32_round(vv.w);
        float4 sv = *(const float4*)&pbase[r * D + c];
        ST[(c + 0) * AP + r] = tf32_round(sv.x);
        ST[(c + 1) * AP + r] = tf32_round(sv.y);
        ST[(c + 2) * AP + r] = tf32_round(sv.z);
        ST[(c + 3) * AP + r] = tf32_round(sv.w);
    }
    if (tid < 64) ssm[tid] = pbase[D * D + tid];
    __syncthreads();

    const int rbase = warp * 16;
    float acc[8][4];

    #pragma unroll
    for (int nf = 0; nf < 8; nf++)
        #pragma unroll
        for (int q = 0; q < 4; q++) acc[nf][q] = 0.0f;

    #pragma unroll
    for (int kf = 0; kf < 8; kf++) {
        const int kc = kf * 8 + tg;
        const float* ap = Qf + (rbase + g) * AP + kc;
        unsigned a0 = __float_as_uint(ap[0]);
        unsigned a1 = __float_as_uint(ap[8 * AP]);
        unsigned a2 = __float_as_uint(ap[4]);
        unsigned a3 = __float_as_uint(ap[8 * AP + 4]);
        #pragma unroll
        for (int nf = 0; nf < 8; nf++) {
            const float* bp = Kf + (nf * 8 + g) * AP + kc;
            unsigned b0 = __float_as_uint(bp[0]);
            unsigned b1 = __float_as_uint(bp[4]);
            MMA_TF32(acc[nf], a0, a1, a2, a3, b0, b1);
        }
    }

    float rsum0 = 0.0f, rsum1 = 0.0f;
    const int row0 = rbase + g;
    const int row1 = rbase + 8 + g;
    #pragma unroll
    for (int nf = 0; nf < 8; nf++) {
        int col = nf * 8 + tg * 2;
        float x0 = (col     <= row0) ? acc[nf][0] : 0.0f;
        float x1 = (col + 1 <= row0) ? acc[nf][1] : 0.0f;
        rsum0 += x0 + x1;
        float2 p0; p0.x = tf32_round(x0); p0.y = tf32_round(x1);
        *(float2*)&Af[row0 * AP + col] = p0;
        float x2 = (col     <= row1) ? acc[nf][2] : 0.0f;
        float x3 = (col + 1 <= row1) ? acc[nf][3] : 0.0f;
        rsum1 += x2 + x3;
        float2 p1; p1.x = tf32_round(x2); p1.y = tf32_round(x3);
        *(float2*)&Af[row1 * AP + col] = p1;
    }
    rsum0 += __shfl_xor_sync(0xffffffffu, rsum0, 1);
    rsum0 += __shfl_xor_sync(0xffffffffu, rsum0, 2);
    rsum1 += __shfl_xor_sync(0xffffffffu, rsum1, 1);
    rsum1 += __shfl_xor_sync(0xffffffffu, rsum1, 2);
    if (tg == 0) { rs[row0] = rsum0; rs[row1] = rsum1; }
    __syncthreads();

    if (tid < 64) {
        float den = rs[tid];
        #pragma unroll 16
        for (int d = 0; d < D; d++) den += Qf[tid * AP + d] * ssm[d];
        dinv[tid] = 1.0f / den;
    }
    __syncthreads();

    #pragma unroll
    for (int nf = 0; nf < 8; nf++)
        #pragma unroll
        for (int q = 0; q < 4; q++) acc[nf][q] = 0.0f;

    #pragma unroll
    for (int kf = 0; kf < 8; kf++) {
        const int kc = kf * 8 + tg;
        const float* ap = Af + (rbase + g) * AP + kc;
        unsigned a0 = __float_as_uint(ap[0]);
        unsigned a1 = __float_as_uint(ap[8 * AP]);
        unsigned a2 = __float_as_uint(ap[4]);
        unsigned a3 = __float_as_uint(ap[8 * AP + 4]);
        #pragma unroll
        for (int nf = 0; nf < 8; nf++) {
            const float* bp = VT + (nf * 8 + g) * AP + kc;
            unsigned b0 = __float_as_uint(bp[0]);
            unsigned b1 = __float_as_uint(bp[4]);
            MMA_TF32(acc[nf], a0, a1, a2, a3, b0, b1);
        }
    }
    #pragma unroll
    for (int kf = 0; kf < 8; kf++) {
        const int kc = kf * 8 + tg;
        const float* ap = Qf + (rbase + g) * AP + kc;
        unsigned a0 = __float_as_uint(ap[0]);
        unsigned a1 = __float_as_uint(ap[8 * AP]);
        unsigned a2 = __float_as_uint(ap[4]);
        unsigned a3 = __float_as_uint(ap[8 * AP + 4]);
        #pragma unroll
        for (int nf = 0; nf < 8; nf++) {
            const float* bp = ST + (nf * 8 + g) * AP + kc;
            unsigned b0 = __float_as_uint(bp[0]);
            unsigned b1 = __float_as_uint(bp[4]);
            MMA_TF32(acc[nf], a0, a1, a2, a3, b0, b1);
        }
    }

    const int n = nh >> 3;
    const int h = nh & 7;
    #pragma unroll
    for (int nf = 0; nf < 8; nf++) {
        int dv = nf * 8 + tg * 2;
        #pragma unroll
        for (int half = 0; half < 2; half++) {
            int i = rbase + half * 8 + g;
            float inv = dinv[i];
            int l = cc * C + i;
            float2 ov;
            ov.x = acc[nf][half * 2 + 0] * inv;
            ov.y = acc[nf][half * 2 + 1] * inv;
            *(float2*)&out[(n * L + l) * DIM + h * D + dv] = ov;
        }
    }
}

// ---------------------------------------------------------------------------
extern "C" void kernel_launch(void* const* d_in, const int* in_sizes, int n_in,
                              void* d_out, int out_size) {
    const float* query   = (const float*)d_in[0];
    const float* key_seq = (const float*)d_in[1];
    const float* Wq      = (const float*)d_in[2];
    const float* Wk      = (const float*)d_in[3];
    const float* Wv      = (const float*)d_in[4];
    float* out = (float*)d_out;

    float *gq, *gk, *gv;
    cudaGetSymbolAddress((void**)&gq, g_q);
    cudaGetSymbolAddress((void**)&gk, g_k);
    cudaGetSymbolAddress((void**)&gv, g_v);

    cudaFuncSetAttribute(gemm_proj_tc,
                         cudaFuncAttributeMaxDynamicSharedMemorySize, GEMM_SMEM);
    cudaFuncSetAttribute(attn_out_tc,
                         cudaFuncAttributeMaxDynamicSharedMemorySize, SMEM_ATTN2);

    const int total4 = (2 * ROWS * DIM + 3 * DIM * DIM) / 4;
    prep_kernel<<<total4 / 256, 256>>>(query, key_seq, Wq, Wk, Wv);

    // position shifters: put gemm_proj_tc at launch slot 4 (the profiled slot)
    dummy_kernel<<<1, 32>>>();
    dummy_kernel<<<1, 32>>>();

    dim3 ggrid(DIM / 128, ROWS / 128, 3);
    gemm_proj_tc<<<ggrid, 256, GEMM_SMEM>>>(gq, gk, gv);

    chunk_state_tc<<<dim3(NC, NH), 128>>>();
    scan_states_kernel<<<dim3(NH, (STSZ + 255) / 256), 256>>>();
    attn_out_tc<<<dim3(NC, NH), 128, SMEM_ATTN2>>>(out);
}